// round 13
// baseline (speedup 1.0000x reference)
#include <cuda_runtime.h>

#define BB 4
#define NSEC 1024
#define NPRIM 256
#define NNODES 1536
#define NH 4
#define OF 32
#define FG 128

// ---------------- scratch (static device memory, no allocs) ----------------
__device__ float g_scratch[6200000];

__device__ __forceinline__ float lrelu(float x) { return x > 0.f ? x : 0.2f * x; }
__device__ __forceinline__ float warpSum(float v) {
    #pragma unroll
    for (int o = 16; o > 0; o >>= 1) v += __shfl_xor_sync(0xffffffffu, v, o);
    return v;
}
// monotone float<->uint encoding for deterministic atomicMax on floats
__device__ __forceinline__ unsigned encf(float f) {
    unsigned u = __float_as_uint(f);
    return (u & 0x80000000u) ? ~u : (u | 0x80000000u);
}
__device__ __forceinline__ float decf(unsigned u) {
    return (u & 0x80000000u) ? __uint_as_float(u ^ 0x80000000u) : __uint_as_float(~u);
}
__device__ __forceinline__ void gbar128(int grp) {
    asm volatile("bar.sync %0, %1;" :: "r"(grp + 1), "r"(128) : "memory");
}

// ======= staged-GEMM compute: 64 k-steps from SMEM, 16 FMA each ============
#define STAGED_COMPUTE()                                                      \
    _Pragma("unroll 16")                                                      \
    for (int k = 0; k < 64; k++) {                                            \
        float4 a4 = *(const float4*)&As[k][ty << 2];                          \
        float4 b4 = *(const float4*)&Bs[k][tx << 2];                          \
        float av[4] = {a4.x, a4.y, a4.z, a4.w};                               \
        float bv[4] = {b4.x, b4.y, b4.z, b4.w};                               \
        _Pragma("unroll")                                                     \
        for (int i = 0; i < 4; i++)                                           \
            _Pragma("unroll")                                                 \
            for (int j = 0; j < 4; j++)                                       \
                acc[i][j] = fmaf(av[i], bv[j], acc[i][j]);                    \
    }

// ---------------- staged GEMM: C = A@B (+bias)(+relu)(+sd & segment-max) ---
// 64x64 tile, BK=64 chunks, 256 threads. Per chunk each thread issues 8
// independent float4 LDGs (MLP=8) prefetched into registers during the
// previous chunk's 1024-FMA compute. 3 barriers total for K=128.
// Row-tile remap: by -> m0 = (by/tilesKeep)*tilesTotal*64 + (by%tilesKeep)*64.
__global__ void __launch_bounds__(256)
gemm_kernel(const float* __restrict__ A, const float* __restrict__ B,
            const float* __restrict__ bias, float* __restrict__ C,
            int N, int K, int tilesKeep, int tilesTotal, int doRelu,
            float* __restrict__ part,
            const float* __restrict__ a_s, const float* __restrict__ a_d,
            float* __restrict__ s, float* __restrict__ d,
            unsigned* __restrict__ smaxu)
{
    __shared__ float As[64][64];      // [k][m] for current chunk
    __shared__ float Bs[64][64];      // [k][n]
    int tid = threadIdx.x;
    int tx = tid & 15, ty = tid >> 4;
    int by = blockIdx.y;
    int bt = by / tilesKeep;
    int m0 = bt * tilesTotal * 64 + (by - bt * tilesKeep) * 64;
    int n0 = blockIdx.x * 64;
    float acc[4][4] = {};
    int ma = tid & 63, kqa = tid >> 6;     // A: row ma, f4 slots kqa+4q
    int kb = tid >> 4, nqb = tid & 15;     // B: rows kb+16q, f4 col nqb
    const float* Arow = A + (size_t)(m0 + ma) * K;
    float4 aR[4], bR[4];

    #define GLOAD(C) {                                                        \
        int koff = (C) * 64;                                                  \
        _Pragma("unroll")                                                     \
        for (int q = 0; q < 4; q++)                                           \
            aR[q] = *(const float4*)(Arow + koff + 4 * (kqa + 4 * q));        \
        _Pragma("unroll")                                                     \
        for (int q = 0; q < 4; q++)                                           \
            bR[q] = *(const float4*)(B + (size_t)(koff + kb + 16 * q) * N + n0 + 4 * nqb); \
    }
    #define GSTS() {                                                          \
        _Pragma("unroll")                                                     \
        for (int q = 0; q < 4; q++) {                                         \
            int kk = 4 * (kqa + 4 * q);                                       \
            As[kk + 0][ma] = aR[q].x; As[kk + 1][ma] = aR[q].y;               \
            As[kk + 2][ma] = aR[q].z; As[kk + 3][ma] = aR[q].w;               \
        }                                                                     \
        _Pragma("unroll")                                                     \
        for (int q = 0; q < 4; q++)                                           \
            *(float4*)&Bs[kb + 16 * q][4 * nqb] = bR[q];                      \
    }

    GLOAD(0)
    GSTS()
    __syncthreads();
    int nC = K >> 6;
    #pragma unroll 1
    for (int c = 0; c < nC; c++) {
        if (c + 1 < nC) GLOAD(c + 1)
        STAGED_COMPUTE()
        if (c + 1 < nC) {
            __syncthreads();
            GSTS()
            __syncthreads();
        }
    }

    float bsum = 0.f;
    #pragma unroll
    for (int i = 0; i < 4; i++) {
        int row = m0 + (ty << 2) + i;
        #pragma unroll
        for (int j = 0; j < 4; j++) {
            int col = n0 + (tx << 2) + j;
            float v = acc[i][j];
            if (bias) v += bias[col];
            if (doRelu) v = fmaxf(v, 0.f);
            C[(size_t)row * N + col] = v;
            bsum += v;
        }
    }

    // Fused attention scalars + encoded segment-max (xp GEMMs, N==128).
    if (s) {
        __shared__ float redm[2][16];
        int b_blk = m0 / NNODES;
        int nb = m0 - b_blk * NNODES;
        int type = nb < NSEC ? 0 : (nb < NSEC + NPRIM ? 1 : 2);
        int h = (n0 >> 5) + (tx >> 3);
        const float* asr = a_s + h * OF + (tx & 7) * 4;
        const float* adr = a_d + h * OF + (tx & 7) * 4;
        float lmax = -1e30f;
        #pragma unroll
        for (int i = 0; i < 4; i++) {
            float ss = 0.f, dd = 0.f;
            #pragma unroll
            for (int j = 0; j < 4; j++) {
                ss = fmaf(acc[i][j], asr[j], ss);
                dd = fmaf(acc[i][j], adr[j], dd);
            }
            ss += __shfl_xor_sync(0xffffffffu, ss, 1);
            ss += __shfl_xor_sync(0xffffffffu, ss, 2);
            ss += __shfl_xor_sync(0xffffffffu, ss, 4);
            dd += __shfl_xor_sync(0xffffffffu, dd, 1);
            dd += __shfl_xor_sync(0xffffffffu, dd, 2);
            dd += __shfl_xor_sync(0xffffffffu, dd, 4);
            if ((tx & 7) == 0) {
                int row = m0 + (ty << 2) + i;
                int n = row - b_blk * NNODES;
                s[(size_t)(b_blk * NH + h) * NNODES + n] = ss;
                d[(size_t)(b_blk * NH + h) * NNODES + n] = dd;
                lmax = fmaxf(lmax, ss);
            }
        }
        if ((tx & 7) == 0) redm[tx >> 3][ty] = lmax;
        __syncthreads();
        if (tid < 2 && type < 2) {
            float m = redm[tid][0];
            #pragma unroll
            for (int q = 1; q < 16; q++) m = fmaxf(m, redm[tid][q]);
            int hh = (n0 >> 5) + tid;
            atomicMax(&smaxu[(b_blk * NH + hh) * 2 + type], encf(m));
        }
    }

    if (part) {
        __shared__ float red[256];
        red[tid] = bsum;
        __syncthreads();
        #pragma unroll
        for (int st = 128; st > 0; st >>= 1) {
            if (tid < st) red[tid] += red[tid + st];
            __syncthreads();
        }
        if (tid == 0) part[blockIdx.y * gridDim.x + blockIdx.x] = red[0];
    }
}

// ---------------- unified aggregation partial core -------------------------
template<int NC>
__device__ __forceinline__ void agg_core(
    const float* __restrict__ xpB, const float* __restrict__ sRow, int srcBase,
    int grp, int lt, float* xSg, float* wTg, float* sSg,
    const float* dS, const float* mS, float acc[4][4], float& zgen)
{
    int txf = lt & 7, tyd = lt >> 3;
    int dstL = lt & 63, halfS = lt >> 6;
    int src0 = lt >> 3, feat0 = (lt & 7) << 2;
    int src1 = (lt + 128) >> 3, feat1 = ((lt + 128) & 7) << 2;

    float4 a0 = *(const float4*)&xpB[(size_t)(srcBase + src0) * FG + feat0];
    float4 a1 = *(const float4*)&xpB[(size_t)(srcBase + src1) * FG + feat1];
    float sv = (lt < 32) ? sRow[srcBase + lt] : 0.f;
    __syncthreads();                       // dS/mS visible; xS free
    #pragma unroll
    for (int c = 0; c < NC; c++) {
        *(float4*)&xSg[src0 * 32 + feat0] = a0;
        *(float4*)&xSg[src1 * 32 + feat1] = a1;
        if (lt < 32) sSg[lt] = sv;
        gbar128(grp);
        if (c + 1 < NC) {
            int nb = srcBase + (c + 1) * 32;
            a0 = *(const float4*)&xpB[(size_t)(nb + src0) * FG + feat0];
            a1 = *(const float4*)&xpB[(size_t)(nb + src1) * FG + feat1];
            sv = (lt < 32) ? sRow[nb + lt] : 0.f;
        }
        {
            float dv_ = dS[dstL], mv_ = mS[dstL];
            #pragma unroll
            for (int r = 0; r < 16; r++) {
                int sidx = halfS * 16 + r;
                float w_ = __expf(lrelu(sSg[sidx] + dv_) - mv_);
                wTg[sidx * 64 + dstL] = w_;
                zgen += w_;
            }
        }
        gbar128(grp);
        #pragma unroll
        for (int k = 0; k < 32; k++) {
            float4 x = *(const float4*)&xSg[k * 32 + 4 * txf];
            float4 w = *(const float4*)&wTg[k * 64 + 4 * tyd];
            acc[0][0] = fmaf(w.x, x.x, acc[0][0]);
            acc[0][1] = fmaf(w.x, x.y, acc[0][1]);
            acc[0][2] = fmaf(w.x, x.z, acc[0][2]);
            acc[0][3] = fmaf(w.x, x.w, acc[0][3]);
            acc[1][0] = fmaf(w.y, x.x, acc[1][0]);
            acc[1][1] = fmaf(w.y, x.y, acc[1][1]);
            acc[1][2] = fmaf(w.y, x.z, acc[1][2]);
            acc[1][3] = fmaf(w.y, x.w, acc[1][3]);
            acc[2][0] = fmaf(w.z, x.x, acc[2][0]);
            acc[2][1] = fmaf(w.z, x.y, acc[2][1]);
            acc[2][2] = fmaf(w.z, x.z, acc[2][2]);
            acc[2][3] = fmaf(w.z, x.w, acc[2][3]);
            acc[3][0] = fmaf(w.w, x.x, acc[3][0]);
            acc[3][1] = fmaf(w.w, x.y, acc[3][1]);
            acc[3][2] = fmaf(w.w, x.z, acc[3][2]);
            acc[3][3] = fmaf(w.w, x.w, acc[3][3]);
        }
        if (c + 1 < NC) gbar128(grp);
    }
}

// ---------------- unified aggregation partial pass (uniform work/block) ----
// grid 1024: blocks [0,512) sec-dst (16 tiles x 2 kblk x 16 bh),
//            blocks [512,1024) beam-dst (4 tiles x 8 kblk x 16 bh).
// Every block processes 128 sources. Layer-2 call uses grid 512 (sec only).
__global__ void agg_part_kernel(const float* __restrict__ xp, const float* __restrict__ s,
                                const float* __restrict__ d, const unsigned* __restrict__ smaxu,
                                float* __restrict__ pfeat, float* __restrict__ pZ,
                                float* __restrict__ pfeatS, float* __restrict__ pZS)
{
    __shared__ float xS[2][32 * 32];
    __shared__ float wT[2][32 * 64];
    __shared__ float sS[2][32];
    __shared__ float dS[64], mS[64];
    __shared__ float comb[64 * 32];
    __shared__ float zS[4][64];
    int tid = threadIdx.x;
    int grp = tid >> 7, lt = tid & 127;
    int bx = blockIdx.x;
    bool isSec = bx < 512;
    int bh, kblk, dst0;
    if (isSec) { bh = bx >> 5; kblk = (bx >> 4) & 1; dst0 = (bx & 15) * 64; }
    else { int e = bx - 512; bh = e >> 5; kblk = (e >> 2) & 7; dst0 = (e & 3) * 64; }
    int b = bh >> 2, h = bh & 3;
    const float* sRow = s + (size_t)bh * NNODES;
    const float* dRow = d + (size_t)bh * NNODES;
    const float* xpB = xp + (size_t)b * NNODES * FG + h * OF;

    if (tid < 64) {
        if (isSec) {
            int i = dst0 + tid;
            float dv = dRow[i];
            dS[tid] = dv;
            mS[tid] = lrelu(fmaxf(decf(smaxu[bh * 2 + 1]), sRow[i]) + dv);
        } else {
            int j = dst0 + tid;
            float dv = dRow[NSEC + j];
            dS[tid] = dv;
            float sP = sRow[NSEC + NPRIM + j];
            float sB = sRow[NSEC + j];
            mS[tid] = lrelu(fmaxf(fmaxf(decf(smaxu[bh * 2]), sP), sB) + dv);
        }
    }
    float acc[4][4] = {};
    float zgen = 0.f;
    int srcBase = isSec ? (NSEC + kblk * 128 + grp * 64) : (kblk * 128 + grp * 64);
    agg_core<2>(xpB, sRow, srcBase, grp, lt,
                xS[grp], wT[grp], sS[grp], dS, mS, acc, zgen);

    int txf = lt & 7, tyd = lt >> 3;
    int dstL = lt & 63, halfS = lt >> 6;
    zS[grp * 2 + halfS][dstL] = zgen;
    if (grp == 1) {
        #pragma unroll
        for (int r = 0; r < 4; r++) {
            float4 o = {acc[r][0], acc[r][1], acc[r][2], acc[r][3]};
            *(float4*)&comb[(4 * tyd + r) * 32 + 4 * txf] = o;
        }
    }
    __syncthreads();
    if (grp == 0) {
        float* pf = isSec ? pfeatS : pfeat;
        float* pz = isSec ? pZS : pZ;
        size_t pbase = isSec ? (size_t)(bh * 2 + kblk) * NSEC
                             : (size_t)(bh * 8 + kblk) * 256;
        #pragma unroll
        for (int r = 0; r < 4; r++) {
            int li = 4 * tyd + r;
            int node = dst0 + li;
            float4 c4 = *(const float4*)&comb[li * 32 + 4 * txf];
            float4 o = {acc[r][0] + c4.x, acc[r][1] + c4.y,
                        acc[r][2] + c4.z, acc[r][3] + c4.w};
            *(float4*)&pf[(pbase + node) * 32 + 4 * txf] = o;
            if (txf == 0)
                pz[pbase + node] = ((zS[0][li] + zS[1][li]) + zS[2][li]) + zS[3][li];
        }
    }
}

// ---------------- unified combine (sec + beam, fixed-order deterministic) --
__global__ void combine_kernel(const float* __restrict__ xp, const float* __restrict__ s,
                               const float* __restrict__ d, const unsigned* __restrict__ smaxu,
                               const float* __restrict__ pfeat, const float* __restrict__ pZ,
                               const float* __restrict__ pfeatS, const float* __restrict__ pZS,
                               const float* __restrict__ bias, float* __restrict__ out)
{
    int tid = threadIdx.x, warp = tid >> 5, lane = tid & 31;
    int w = blockIdx.x * 8 + warp;
    int bh = w / 1280;
    int rem = w - bh * 1280;
    int b = bh >> 2, h = bh & 3;
    const float* sRow = s + (size_t)bh * NNODES;
    const float* dRow = d + (size_t)bh * NNODES;
    const float* xpB = xp + (size_t)b * NNODES * FG + h * OF;
    float bval = bias[h * OF + lane];
    if (rem < NSEC) {
        int i = rem;
        float dv = dRow[i];
        float m = lrelu(fmaxf(decf(smaxu[bh * 2 + 1]), sRow[i]) + dv);  // == part pass
        float ws = __expf(lrelu(sRow[i] + dv) - m);
        size_t p0 = (size_t)bh * 2 * NSEC + i;
        float Z = pZS[p0] + pZS[p0 + NSEC] + ws;
        float acc = pfeatS[p0 * 32 + lane] + pfeatS[(p0 + NSEC) * 32 + lane];
        acc = fmaf(ws, xpB[(size_t)i * FG + lane], acc);
        float v = acc / Z + bval;
        out[(size_t)b * NNODES * FG + (size_t)i * FG + h * OF + lane] = fmaxf(v, 0.f);
    } else {
        int j = rem - NSEC;
        float dv = dRow[NSEC + j];
        float sP = sRow[NSEC + NPRIM + j];
        float sB = sRow[NSEC + j];
        float m = lrelu(fmaxf(fmaxf(decf(smaxu[bh * 2]), sP), sB) + dv); // == part pass
        float wp = __expf(lrelu(sP + dv) - m);
        float ws = __expf(lrelu(sB + dv) - m);
        size_t q0 = (size_t)(bh * 8) * 256 + j;
        float Z = 0.f, acc = 0.f;
        #pragma unroll
        for (int k = 0; k < 8; k++) {
            Z += pZ[q0 + k * 256];
            acc += pfeat[(q0 + k * 256) * 32 + lane];
        }
        Z += wp + ws;
        acc = fmaf(wp, xpB[(size_t)(NSEC + NPRIM + j) * FG + lane], acc);
        acc = fmaf(ws, xpB[(size_t)(NSEC + j) * FG + lane], acc);
        float v = acc / Z + bval;
        out[(size_t)b * NNODES * FG + (size_t)(NSEC + j) * FG + h * OF + lane] = fmaxf(v, 0.f);
    }
}

// ---------------- staged FC0 with fused layer-2 sec combine ----------------
// Same BK=64 staging; B prefetched into regs; A built by combine math at
// stage time (one exposed load latency per chunk boundary, nC=2).
__global__ void __launch_bounds__(256)
fc0_fused_kernel(const float* __restrict__ pfeatS, const float* __restrict__ pZS,
                 const float* __restrict__ xp2, const float* __restrict__ s2,
                 const float* __restrict__ d2, const unsigned* __restrict__ smax2,
                 const float* __restrict__ gatB,
                 const float* __restrict__ B, const float* __restrict__ bias,
                 float* __restrict__ C)
{
    const int N = 256, K = 128;
    __shared__ float As[64][64];
    __shared__ float Bs[64][64];
    int tid = threadIdx.x;
    int tx = tid & 15, ty = tid >> 4;
    int m0 = blockIdx.y * 64;
    int n0 = blockIdx.x * 64;
    float acc[4][4] = {};
    int ma = tid & 63, kqa = tid >> 6;
    int kb = tid >> 4, nqb = tid & 15;
    float4 bR[4];

    int r = m0 + ma;
    int b = r >> 10, i_ = r & 1023;
    float wsv[4], invZv[4];
    #pragma unroll
    for (int h = 0; h < 4; h++) {
        int bh = b * 4 + h;
        float sv = s2[(size_t)bh * NNODES + i_];
        float dv = d2[(size_t)bh * NNODES + i_];
        float m = lrelu(fmaxf(decf(smax2[bh * 2 + 1]), sv) + dv);   // == part pass
        float w = __expf(lrelu(sv + dv) - m);
        size_t p0 = ((size_t)bh * 2) * NSEC + i_;
        float Z = pZS[p0] + pZS[p0 + NSEC] + w;
        wsv[h] = w; invZv[h] = 1.f / Z;
    }
    size_t xrow = ((size_t)b * NNODES + i_) * FG;

    #define F0BLOAD(C) {                                                      \
        int koff = (C) * 64;                                                  \
        _Pragma("unroll")                                                     \
        for (int q = 0; q < 4; q++)                                           \
            bR[q] = *(const float4*)(B + (size_t)(koff + kb + 16 * q) * N + n0 + 4 * nqb); \
    }
    #define F0ASTAGE(C) {                                                     \
        _Pragma("unroll")                                                     \
        for (int q = 0; q < 4; q++) {                                         \
            int f0 = (C) * 64 + 4 * (kqa + 4 * q);                            \
            int hh = f0 >> 5; int fh = f0 & 31;                               \
            size_t p0_ = ((size_t)(b * 8 + hh * 2)) * NSEC + i_;              \
            float4 pf0 = *(const float4*)&pfeatS[p0_ * 32 + fh];              \
            float4 pf1 = *(const float4*)&pfeatS[(p0_ + NSEC) * 32 + fh];     \
            float4 xv = *(const float4*)&xp2[xrow + hh * 32 + fh];            \
            float4 gb = *(const float4*)&gatB[hh * 32 + fh];                  \
            float w_ = wsv[hh], z_ = invZv[hh];                               \
            int kk = f0 - (C) * 64;                                           \
            As[kk + 0][ma] = fmaxf((pf0.x + pf1.x + w_ * xv.x) * z_ + gb.x, 0.f); \
            As[kk + 1][ma] = fmaxf((pf0.y + pf1.y + w_ * xv.y) * z_ + gb.y, 0.f); \
            As[kk + 2][ma] = fmaxf((pf0.z + pf1.z + w_ * xv.z) * z_ + gb.z, 0.f); \
            As[kk + 3][ma] = fmaxf((pf0.w + pf1.w + w_ * xv.w) * z_ + gb.w, 0.f); \
        }                                                                     \
    }
    #define F0BSTS() {                                                        \
        _Pragma("unroll")                                                     \
        for (int q = 0; q < 4; q++)                                           \
            *(float4*)&Bs[kb + 16 * q][4 * nqb] = bR[q];                      \
    }

    F0BLOAD(0)
    F0ASTAGE(0)
    F0BSTS()
    __syncthreads();
    const int nC = K >> 6;       // 2
    #pragma unroll 1
    for (int c = 0; c < nC; c++) {
        if (c + 1 < nC) F0BLOAD(c + 1)
        STAGED_COMPUTE()
        if (c + 1 < nC) {
            __syncthreads();
            F0ASTAGE(c + 1)
            F0BSTS()
            __syncthreads();
        }
    }

    #pragma unroll
    for (int i = 0; i < 4; i++) {
        int row = m0 + (ty << 2) + i;
        #pragma unroll
        for (int j = 0; j < 4; j++) {
            int col = n0 + (tx << 2) + j;
            float v = acc[i][j] + bias[col];
            C[(size_t)row * N + col] = fmaxf(v, 0.f);
        }
    }
}

// ---------------- fused ratio + scale/threshold + smax reset ---------------
__global__ void scale_ratio_kernel(float4* __restrict__ C, const float* __restrict__ pP,
                                   const float* __restrict__ pT, const float* __restrict__ part,
                                   unsigned* __restrict__ smaxu)
{
    __shared__ float shPs, shPps;
    int tid = threadIdx.x;
    int idx = blockIdx.x * 256 + tid;        // 262144 float4s
    int b = idx >> 16;
    int warp = tid >> 5, lane = tid & 31;
    if (blockIdx.x == 0 && tid >= 128 && tid < 192)
        smaxu[tid - 128] = 0u;               // reset for next replay
    if (warp == 0) {
        float ps = part[b * 64 + lane] + part[b * 64 + 32 + lane];
        ps = warpSum(ps);
        if (lane == 0) shPs = ps;
    } else if (warp == 1) {
        float pps = 0.f;
        #pragma unroll
        for (int k = 0; k < 8; k++) pps += pP[b * 256 + lane + 32 * k];
        pps = warpSum(pps);
        if (lane == 0) shPps = pps;
    }
    __syncthreads();
    float rr = fminf(fmaxf(pT[0] - shPps, 0.f) / (shPs + 1e-5f), 1.f);
    float4 v = C[idx];
    v.x *= rr; v.y *= rr; v.z *= rr; v.w *= rr;
    v.x = (v.x > 0.001f) ? v.x : 0.f;
    v.y = (v.y > 0.001f) ? v.y : 0.f;
    v.z = (v.z > 0.001f) ? v.z : 0.f;
    v.w = (v.w > 0.001f) ? v.w : 0.f;
    C[idx] = v;
}

// ---------------- launch ----------------------------------------------------
extern "C" void kernel_launch(void* const* d_in, const int* in_sizes, int n_in,
                              void* d_out, int out_size)
{
    const float* h   = (const float*)d_in[0];
    const float* pP  = (const float*)d_in[1];
    const float* pT  = (const float*)d_in[2];
    const float* W0  = (const float*)d_in[3];
    const float* b0  = (const float*)d_in[4];
    const float* as0 = (const float*)d_in[5];
    const float* ad0 = (const float*)d_in[6];
    const float* W1  = (const float*)d_in[7];
    const float* b1  = (const float*)d_in[8];
    const float* as1 = (const float*)d_in[9];
    const float* ad1 = (const float*)d_in[10];
    const float* Wf0 = (const float*)d_in[11];
    const float* bf0 = (const float*)d_in[12];
    const float* Wf1 = (const float*)d_in[13];
    const float* bf1 = (const float*)d_in[14];
    float* out = (float*)d_out;

    float* base = nullptr;
    cudaGetSymbolAddress((void**)&base, g_scratch);
    float* xp1    = base;                   // 786432
    float* x1     = xp1 + 786432;           // 786432
    float* xp2    = x1 + 786432;            // 786432
    float* z      = xp2 + 786432;           // 1048576
    float* s1     = z + 1048576;            // 24576
    float* d1     = s1 + 24576;
    float* s2     = d1 + 24576;
    float* d2     = s2 + 24576;
    unsigned* smaxu = (unsigned*)(d2 + 24576);  // 64
    float* pfeat  = d2 + 24576 + 64;        // beam partials: 16*8*256*32 = 1048576
    float* pZ     = pfeat + 1048576;        // 32768
    float* pfeatS = pZ + 32768;             // sec partials: 16*2*1024*32 = 1048576
    float* pZS    = pfeatS + 1048576;       // 32768
    float* part   = pZS + 32768;            // 256
    unsigned* smax1u = smaxu;
    unsigned* smax2u = smaxu + 32;

    // 1. Layer-1 GEMM (staged; fused sd + segment-max)
    gemm_kernel<<<dim3(2, 96), 256>>>(h, W0, nullptr, xp1, FG, FG, 24, 24, 0,
                                      nullptr, as0, ad0, s1, d1, smax1u);
    // 2. Unified layer-1 aggregation partials (uniform 1024-block wave)
    agg_part_kernel<<<1024, 256>>>(xp1, s1, d1, smax1u, pfeat, pZ, pfeatS, pZS);
    // 3. Unified combine (sec + beam) -> x1
    combine_kernel<<<2560, 256>>>(xp1, s1, d1, smax1u, pfeat, pZ, pfeatS, pZS, b0, x1);
    // 4. Layer-2 GEMM (staged; prim tiles skipped; fused sd)
    gemm_kernel<<<dim3(2, 80), 256>>>(x1, W1, nullptr, xp2, FG, FG, 20, 24, 0,
                                      nullptr, as1, ad1, s2, d2, smax2u);
    // 5. Layer-2 sec aggregation partials
    agg_part_kernel<<<512, 256>>>(xp2, s2, d2, smax2u, pfeat, pZ, pfeatS, pZS);
    // 6. FC0 (staged; layer-2 sec combine fused in A-loader)
    fc0_fused_kernel<<<dim3(4, 64), 256>>>(pfeatS, pZS, xp2, s2, d2, smax2u, b1,
                                           Wf0, bf0, z);
    // 7. FC1 (staged, K=256; + per-block partial sums)
    gemm_kernel<<<dim3(4, 64), 256>>>(z, Wf1, bf1, out, 256, 256, 64, 64, 1,
                                      part, nullptr, nullptr, nullptr, nullptr, nullptr);
    // 8. Fused ratio + threshold (+ smax reset for next replay)
    scale_ratio_kernel<<<1024, 256>>>((float4*)out, pP, pT, part, smaxu);
}

// round 14
// speedup vs baseline: 1.1188x; 1.1188x over previous
#include <cuda_runtime.h>

#define BB 4
#define NSEC 1024
#define NPRIM 256
#define NNODES 1536
#define NH 4
#define OF 32
#define FG 128

// ---------------- scratch (static device memory, no allocs) ----------------
__device__ float g_scratch[6200000];

__device__ __forceinline__ float lrelu(float x) { return x > 0.f ? x : 0.2f * x; }
__device__ __forceinline__ float warpSum(float v) {
    #pragma unroll
    for (int o = 16; o > 0; o >>= 1) v += __shfl_xor_sync(0xffffffffu, v, o);
    return v;
}
// monotone float<->uint encoding for deterministic atomicMax on floats
__device__ __forceinline__ unsigned encf(float f) {
    unsigned u = __float_as_uint(f);
    return (u & 0x80000000u) ? ~u : (u | 0x80000000u);
}
__device__ __forceinline__ float decf(unsigned u) {
    return (u & 0x80000000u) ? __uint_as_float(u ^ 0x80000000u) : __uint_as_float(~u);
}

// ---------------- GEMM: C = A@B (+bias)(+relu)(+fused sd & segment-max) ----
// 64x64 tile, BK=16, 256 threads, 4x4 microtile, double-buffered SMEM.
// Row-tile remap: by -> m0 = (by/tilesKeep)*tilesTotal*64
//                         + (tileBase + by%tilesKeep)*64.
__global__ void gemm_kernel(const float* __restrict__ A, const float* __restrict__ B,
                            const float* __restrict__ bias, float* __restrict__ C,
                            int N, int K, int tilesKeep, int tilesTotal, int tileBase,
                            int doRelu, float* __restrict__ part,
                            const float* __restrict__ a_s, const float* __restrict__ a_d,
                            float* __restrict__ s, float* __restrict__ d,
                            unsigned* __restrict__ smaxu)
{
    __shared__ float As[2][16][64];
    __shared__ float Bs[2][16][64];
    int tid = threadIdx.x;
    int tx = tid & 15, ty = tid >> 4;
    int by = blockIdx.y;
    int bt = by / tilesKeep;
    int m0 = bt * tilesTotal * 64 + (tileBase + by - bt * tilesKeep) * 64;
    int n0 = blockIdx.x * 64;
    float acc[4][4] = {};
    int am = tid >> 2, ak = (tid & 3) << 2;
    int bk = tid >> 4, bn = (tid & 15) << 2;
    const float* Abase = A + (size_t)(m0 + am) * K + ak;
    const float* Bbase = B + (size_t)bk * N + n0 + bn;

    {
        float4 a = *(const float4*)(Abase);
        float4 bb = *(const float4*)(Bbase);
        As[0][ak + 0][am] = a.x; As[0][ak + 1][am] = a.y;
        As[0][ak + 2][am] = a.z; As[0][ak + 3][am] = a.w;
        *(float4*)&Bs[0][bk][bn] = bb;
    }
    __syncthreads();
    int nT = K >> 4;
    #pragma unroll 2
    for (int it = 1; it < nT; it++) {
        float4 a2 = *(const float4*)(Abase + it * 16);
        float4 b2 = *(const float4*)(Bbase + (size_t)it * 16 * N);
        int pb = (it - 1) & 1;
        #pragma unroll
        for (int k = 0; k < 16; k++) {
            float4 a4 = *(const float4*)&As[pb][k][ty << 2];
            float4 b4 = *(const float4*)&Bs[pb][k][tx << 2];
            float av[4] = {a4.x, a4.y, a4.z, a4.w};
            float bv[4] = {b4.x, b4.y, b4.z, b4.w};
            #pragma unroll
            for (int i = 0; i < 4; i++)
                #pragma unroll
                for (int j = 0; j < 4; j++)
                    acc[i][j] = fmaf(av[i], bv[j], acc[i][j]);
        }
        int cb = it & 1;
        As[cb][ak + 0][am] = a2.x; As[cb][ak + 1][am] = a2.y;
        As[cb][ak + 2][am] = a2.z; As[cb][ak + 3][am] = a2.w;
        *(float4*)&Bs[cb][bk][bn] = b2;
        __syncthreads();
    }
    {
        int pb = (nT - 1) & 1;
        #pragma unroll
        for (int k = 0; k < 16; k++) {
            float4 a4 = *(const float4*)&As[pb][k][ty << 2];
            float4 b4 = *(const float4*)&Bs[pb][k][tx << 2];
            float av[4] = {a4.x, a4.y, a4.z, a4.w};
            float bv[4] = {b4.x, b4.y, b4.z, b4.w};
            #pragma unroll
            for (int i = 0; i < 4; i++)
                #pragma unroll
                for (int j = 0; j < 4; j++)
                    acc[i][j] = fmaf(av[i], bv[j], acc[i][j]);
        }
    }

    float bsum = 0.f;
    #pragma unroll
    for (int i = 0; i < 4; i++) {
        int row = m0 + (ty << 2) + i;
        #pragma unroll
        for (int j = 0; j < 4; j++) {
            int col = n0 + (tx << 2) + j;
            float v = acc[i][j];
            if (bias) v += bias[col];
            if (doRelu) v = fmaxf(v, 0.f);
            C[(size_t)row * N + col] = v;
            bsum += v;
        }
    }

    // Fused attention scalars + encoded segment-max (xp GEMMs, N==128).
    if (s) {
        __shared__ float redm[2][16];
        int b_blk = m0 / NNODES;
        int nb = m0 - b_blk * NNODES;
        int type = nb < NSEC ? 0 : (nb < NSEC + NPRIM ? 1 : 2);
        int h = (n0 >> 5) + (tx >> 3);
        const float* asr = a_s + h * OF + (tx & 7) * 4;
        const float* adr = a_d + h * OF + (tx & 7) * 4;
        float lmax = -1e30f;
        #pragma unroll
        for (int i = 0; i < 4; i++) {
            float ss = 0.f, dd = 0.f;
            #pragma unroll
            for (int j = 0; j < 4; j++) {
                ss = fmaf(acc[i][j], asr[j], ss);
                dd = fmaf(acc[i][j], adr[j], dd);
            }
            ss += __shfl_xor_sync(0xffffffffu, ss, 1);
            ss += __shfl_xor_sync(0xffffffffu, ss, 2);
            ss += __shfl_xor_sync(0xffffffffu, ss, 4);
            dd += __shfl_xor_sync(0xffffffffu, dd, 1);
            dd += __shfl_xor_sync(0xffffffffu, dd, 2);
            dd += __shfl_xor_sync(0xffffffffu, dd, 4);
            if ((tx & 7) == 0) {
                int row = m0 + (ty << 2) + i;
                int n = row - b_blk * NNODES;
                s[(size_t)(b_blk * NH + h) * NNODES + n] = ss;
                d[(size_t)(b_blk * NH + h) * NNODES + n] = dd;
                lmax = fmaxf(lmax, ss);
            }
        }
        if ((tx & 7) == 0) redm[tx >> 3][ty] = lmax;
        __syncthreads();
        if (tid < 2 && type < 2) {
            float m = redm[tid][0];
            #pragma unroll
            for (int q = 1; q < 16; q++) m = fmaxf(m, redm[tid][q]);
            int hh = (n0 >> 5) + tid;
            atomicMax(&smaxu[(b_blk * NH + hh) * 2 + type], encf(m));
        }
    }

    if (part) {
        __shared__ float red[256];
        red[tid] = bsum;
        __syncthreads();
        #pragma unroll
        for (int st = 128; st > 0; st >>= 1) {
            if (tid < st) red[tid] += red[tid + st];
            __syncthreads();
        }
        if (tid == 0) part[blockIdx.y * gridDim.x + blockIdx.x] = red[0];
    }
}

// ====== agg helpers ========================================================
#define GBAR() asm volatile("bar.sync %0, %1;" :: "r"(grp + 1), "r"(128) : "memory")

#define AGG_FMA_LOOP(GRP)                                                     \
    _Pragma("unroll")                                                         \
    for (int k = 0; k < 32; k++) {                                            \
        float4 x = *(const float4*)&xS[GRP][k * 32 + 4 * txf];                \
        float4 w = *(const float4*)&wT[GRP][k * 64 + 4 * tyd];                \
        acc[0][0] = fmaf(w.x, x.x, acc[0][0]);                                \
        acc[0][1] = fmaf(w.x, x.y, acc[0][1]);                                \
        acc[0][2] = fmaf(w.x, x.z, acc[0][2]);                                \
        acc[0][3] = fmaf(w.x, x.w, acc[0][3]);                                \
        acc[1][0] = fmaf(w.y, x.x, acc[1][0]);                                \
        acc[1][1] = fmaf(w.y, x.y, acc[1][1]);                                \
        acc[1][2] = fmaf(w.y, x.z, acc[1][2]);                                \
        acc[1][3] = fmaf(w.y, x.w, acc[1][3]);                                \
        acc[2][0] = fmaf(w.z, x.x, acc[2][0]);                                \
        acc[2][1] = fmaf(w.z, x.y, acc[2][1]);                                \
        acc[2][2] = fmaf(w.z, x.z, acc[2][2]);                                \
        acc[2][3] = fmaf(w.z, x.w, acc[2][3]);                                \
        acc[3][0] = fmaf(w.w, x.x, acc[3][0]);                                \
        acc[3][1] = fmaf(w.w, x.y, acc[3][1]);                                \
        acc[3][2] = fmaf(w.w, x.z, acc[3][2]);                                \
        acc[3][3] = fmaf(w.w, x.w, acc[3][3]);                                \
    }

#define AGG_GEN_W(GRP)                                                        \
    {                                                                         \
        float dv_ = dS[dstL], mv_ = mS[dstL];                                 \
        _Pragma("unroll")                                                     \
        for (int r = 0; r < 16; r++) {                                        \
            int sidx = halfS * 16 + r;                                        \
            float w_ = __expf(lrelu(sS[GRP][sidx] + dv_) - mv_);              \
            wT[GRP][sidx * 64 + dstL] = w_;                                   \
            zgen += w_;                                                       \
        }                                                                     \
    }

// ---------------- sec-destination aggregation, k-split partial pass --------
// grid (16 dst-tiles, 2 kblk, 16 bh), 256 thr = 2 independent warp-groups
// (named barriers), each over 2 chunks of 32 beam srcs, chunk-1 prefetched.
__global__ void sec_agg_part_kernel(const float* __restrict__ xp, const float* __restrict__ s,
                                    const float* __restrict__ d, const unsigned* __restrict__ smaxu,
                                    float* __restrict__ pfeatS, float* __restrict__ pZS)
{
    __shared__ float xS[2][32 * 32];
    __shared__ float wT[2][32 * 64];
    __shared__ float sS[2][32];
    __shared__ float dS[64], mS[64];
    __shared__ float comb[64 * 32];
    __shared__ float zS[4][64];
    int tid = threadIdx.x;
    int grp = tid >> 7, lt = tid & 127;
    int bh = blockIdx.z;
    int b = bh >> 2, h = bh & 3;
    int dst0 = blockIdx.x * 64;
    int kblk = blockIdx.y;
    const float* sRow = s + (size_t)bh * NNODES;
    const float* dRow = d + (size_t)bh * NNODES;
    const float* xpB = xp + (size_t)b * NNODES * FG + h * OF;

    if (tid < 64) {
        int i = dst0 + tid;
        float dv = dRow[i];
        dS[tid] = dv;
        mS[tid] = lrelu(fmaxf(decf(smaxu[bh * 2 + 1]), sRow[i]) + dv);
    }
    int txf = lt & 7, tyd = lt >> 3;
    int dstL = lt & 63, halfS = lt >> 6;
    int src0 = lt >> 3, feat0 = (lt & 7) << 2;
    int src1 = (lt + 128) >> 3, feat1 = ((lt + 128) & 7) << 2;
    int base0 = NSEC + kblk * 128 + grp * 64;
    float acc[4][4] = {};
    float zgen = 0.f;

    float4 a00 = *(const float4*)&xpB[(size_t)(base0 + src0) * FG + feat0];
    float4 a01 = *(const float4*)&xpB[(size_t)(base0 + src1) * FG + feat1];
    float s0v = (lt < 32) ? sRow[base0 + lt] : 0.f;
    __syncthreads();                      // dS/mS visible to all
    *(float4*)&xS[grp][src0 * 32 + feat0] = a00;
    *(float4*)&xS[grp][src1 * 32 + feat1] = a01;
    if (lt < 32) sS[grp][lt] = s0v;
    GBAR();
    float4 a10 = *(const float4*)&xpB[(size_t)(base0 + 32 + src0) * FG + feat0];
    float4 a11 = *(const float4*)&xpB[(size_t)(base0 + 32 + src1) * FG + feat1];
    float s1v = (lt < 32) ? sRow[base0 + 32 + lt] : 0.f;
    AGG_GEN_W(grp)
    GBAR();
    AGG_FMA_LOOP(grp)
    GBAR();
    *(float4*)&xS[grp][src0 * 32 + feat0] = a10;
    *(float4*)&xS[grp][src1 * 32 + feat1] = a11;
    if (lt < 32) sS[grp][lt] = s1v;
    GBAR();
    AGG_GEN_W(grp)
    GBAR();
    AGG_FMA_LOOP(grp)

    zS[grp * 2 + halfS][dstL] = zgen;
    if (grp == 1) {
        #pragma unroll
        for (int r = 0; r < 4; r++) {
            float4 o = {acc[r][0], acc[r][1], acc[r][2], acc[r][3]};
            *(float4*)&comb[(4 * tyd + r) * 32 + 4 * txf] = o;
        }
    }
    __syncthreads();
    if (grp == 0) {
        size_t pbase = (size_t)(bh * 2 + kblk) * NSEC;
        #pragma unroll
        for (int r = 0; r < 4; r++) {
            int li = 4 * tyd + r;
            int i = dst0 + li;
            float4 c4 = *(const float4*)&comb[li * 32 + 4 * txf];
            float4 o = {acc[r][0] + c4.x, acc[r][1] + c4.y,
                        acc[r][2] + c4.z, acc[r][3] + c4.w};
            *(float4*)&pfeatS[(pbase + i) * 32 + 4 * txf] = o;
            if (txf == 0)
                pZS[pbase + i] = ((zS[0][li] + zS[1][li]) + zS[2][li]) + zS[3][li];
        }
    }
}

// ---------------- sec combine, layer 1 only (fixed-order deterministic) ----
__global__ void sec_combine_kernel(const float* __restrict__ xp, const float* __restrict__ s,
                                   const float* __restrict__ d, const unsigned* __restrict__ smaxu,
                                   const float* __restrict__ pfeatS, const float* __restrict__ pZS,
                                   const float* __restrict__ bias, float* __restrict__ out,
                                   int outStrideB)
{
    int tid = threadIdx.x, warp = tid >> 5, lane = tid & 31;
    int bh = blockIdx.y, b = bh >> 2, h = bh & 3;
    int i = blockIdx.x * 8 + warp;
    const float* sRow = s + (size_t)bh * NNODES;
    const float* dRow = d + (size_t)bh * NNODES;
    float dv = dRow[i];
    float m = lrelu(fmaxf(decf(smaxu[bh * 2 + 1]), sRow[i]) + dv);  // identical to part pass
    float ws = __expf(lrelu(sRow[i] + dv) - m);
    size_t p0 = (size_t)bh * 2 * NSEC + i;
    float Z = pZS[p0] + pZS[p0 + NSEC] + ws;
    float acc = pfeatS[p0 * 32 + lane] + pfeatS[(p0 + NSEC) * 32 + lane];
    const float* xpB = xp + (size_t)b * NNODES * FG + h * OF;
    acc = fmaf(ws, xpB[(size_t)i * FG + lane], acc);
    float v = acc / Z + bias[h * OF + lane];
    out[(size_t)b * outStrideB + (size_t)i * FG + h * OF + lane] = fmaxf(v, 0.f);
}

// ---------------- beam-destination aggregation, k-split partial pass -------
// grid (4 dst-tiles, 8 kblk, 16 bh), 256 thr; same named-barrier + prefetch.
__global__ void beam_agg_part_kernel(const float* __restrict__ xp, const float* __restrict__ s,
                                     const float* __restrict__ d, const unsigned* __restrict__ smaxu,
                                     float* __restrict__ pfeat, float* __restrict__ pZ)
{
    __shared__ float xS[2][32 * 32];
    __shared__ float wT[2][32 * 64];
    __shared__ float sS[2][32];
    __shared__ float dS[64], mS[64];
    __shared__ float comb[64 * 32];
    __shared__ float zS[4][64];
    int tid = threadIdx.x;
    int grp = tid >> 7, lt = tid & 127;
    int bh = blockIdx.z;
    int b = bh >> 2, h = bh & 3;
    int dst0 = blockIdx.x * 64;
    int kblk = blockIdx.y;
    const float* sRow = s + (size_t)bh * NNODES;
    const float* dRow = d + (size_t)bh * NNODES;
    const float* xpB = xp + (size_t)b * NNODES * FG + h * OF;

    if (tid < 64) {
        int j = dst0 + tid;
        float dv = dRow[NSEC + j];
        dS[tid] = dv;
        float sP = sRow[NSEC + NPRIM + j];
        float sB = sRow[NSEC + j];
        mS[tid] = lrelu(fmaxf(fmaxf(decf(smaxu[bh * 2]), sP), sB) + dv);
    }
    int txf = lt & 7, tyd = lt >> 3;
    int dstL = lt & 63, halfS = lt >> 6;
    int src0 = lt >> 3, feat0 = (lt & 7) << 2;
    int src1 = (lt + 128) >> 3, feat1 = ((lt + 128) & 7) << 2;
    int base0 = kblk * 128 + grp * 64;
    float acc[4][4] = {};
    float zgen = 0.f;

    float4 a00 = *(const float4*)&xpB[(size_t)(base0 + src0) * FG + feat0];
    float4 a01 = *(const float4*)&xpB[(size_t)(base0 + src1) * FG + feat1];
    float s0v = (lt < 32) ? sRow[base0 + lt] : 0.f;
    __syncthreads();
    *(float4*)&xS[grp][src0 * 32 + feat0] = a00;
    *(float4*)&xS[grp][src1 * 32 + feat1] = a01;
    if (lt < 32) sS[grp][lt] = s0v;
    GBAR();
    float4 a10 = *(const float4*)&xpB[(size_t)(base0 + 32 + src0) * FG + feat0];
    float4 a11 = *(const float4*)&xpB[(size_t)(base0 + 32 + src1) * FG + feat1];
    float s1v = (lt < 32) ? sRow[base0 + 32 + lt] : 0.f;
    AGG_GEN_W(grp)
    GBAR();
    AGG_FMA_LOOP(grp)
    GBAR();
    *(float4*)&xS[grp][src0 * 32 + feat0] = a10;
    *(float4*)&xS[grp][src1 * 32 + feat1] = a11;
    if (lt < 32) sS[grp][lt] = s1v;
    GBAR();
    AGG_GEN_W(grp)
    GBAR();
    AGG_FMA_LOOP(grp)

    zS[grp * 2 + halfS][dstL] = zgen;
    if (grp == 1) {
        #pragma unroll
        for (int r = 0; r < 4; r++) {
            float4 o = {acc[r][0], acc[r][1], acc[r][2], acc[r][3]};
            *(float4*)&comb[(4 * tyd + r) * 32 + 4 * txf] = o;
        }
    }
    __syncthreads();
    if (grp == 0) {
        size_t pbase = (size_t)(bh * 8 + kblk) * 256;
        #pragma unroll
        for (int r = 0; r < 4; r++) {
            int li = 4 * tyd + r;
            int j = dst0 + li;
            float4 c4 = *(const float4*)&comb[li * 32 + 4 * txf];
            float4 o = {acc[r][0] + c4.x, acc[r][1] + c4.y,
                        acc[r][2] + c4.z, acc[r][3] + c4.w};
            *(float4*)&pfeat[(pbase + j) * 32 + 4 * txf] = o;
            if (txf == 0)
                pZ[pbase + j] = ((zS[0][li] + zS[1][li]) + zS[2][li]) + zS[3][li];
        }
    }
}

// ---------------- beam combine (fixed-order deterministic) -----------------
__global__ void beam_combine_kernel(const float* __restrict__ xp, const float* __restrict__ s,
                                    const float* __restrict__ d, const unsigned* __restrict__ smaxu,
                                    const float* __restrict__ pfeat, const float* __restrict__ pZ,
                                    const float* __restrict__ bias, float* __restrict__ out)
{
    int tid = threadIdx.x, warp = tid >> 5, lane = tid & 31;
    int bh = blockIdx.y, b = bh >> 2, h = bh & 3;
    int j = blockIdx.x * 8 + warp;
    const float* sRow = s + (size_t)bh * NNODES;
    const float* dRow = d + (size_t)bh * NNODES;
    float dv = dRow[NSEC + j];
    float sP = sRow[NSEC + NPRIM + j];
    float sB = sRow[NSEC + j];
    float m = lrelu(fmaxf(fmaxf(decf(smaxu[bh * 2]), sP), sB) + dv);
    float wp = __expf(lrelu(sP + dv) - m);
    float ws = __expf(lrelu(sB + dv) - m);
    size_t p0 = (size_t)bh * 8 * 256 + j;
    float Z = 0.f, acc = 0.f;
    #pragma unroll
    for (int k = 0; k < 8; k++) {
        Z += pZ[p0 + k * 256];
        acc += pfeat[(p0 + k * 256) * 32 + lane];
    }
    Z += wp + ws;
    const float* xpB = xp + (size_t)b * NNODES * FG + h * OF;
    acc = fmaf(wp, xpB[(size_t)(NSEC + NPRIM + j) * FG + lane], acc);
    acc = fmaf(ws, xpB[(size_t)(NSEC + j) * FG + lane], acc);
    float v = acc / Z + bias[h * OF + lane];
    out[(size_t)b * NNODES * FG + (size_t)(NSEC + j) * FG + h * OF + lane] = fmaxf(v, 0.f);
}

// ---------------- FC0 with fused layer-2 sec combine in the A-loader -------
// z[4096,256] = relu( combine(pfeatS,pZS,xp2,...)[4096,128] @ Wf0 + bf0 )
__global__ void fc0_fused_kernel(const float* __restrict__ pfeatS, const float* __restrict__ pZS,
                                 const float* __restrict__ xp2, const float* __restrict__ s2,
                                 const float* __restrict__ d2, const unsigned* __restrict__ smax2,
                                 const float* __restrict__ gatB,
                                 const float* __restrict__ B, const float* __restrict__ bias,
                                 float* __restrict__ C)
{
    const int N = 256, K = 128;
    __shared__ float As[2][16][64];
    __shared__ float Bs[2][16][64];
    int tid = threadIdx.x;
    int tx = tid & 15, ty = tid >> 4;
    int m0 = blockIdx.y * 64;
    int n0 = blockIdx.x * 64;
    float acc[4][4] = {};
    int am = tid >> 2, ak = (tid & 3) << 2;
    int bk = tid >> 4, bn = (tid & 15) << 2;
    const float* Bbase = B + (size_t)bk * N + n0 + bn;

    int r = m0 + am;
    int b = r >> 10, i_ = r & 1023;
    float wsv[4], invZv[4];
    #pragma unroll
    for (int h = 0; h < 4; h++) {
        int bh = b * 4 + h;
        float sv = s2[(size_t)bh * NNODES + i_];
        float dv = d2[(size_t)bh * NNODES + i_];
        float m = lrelu(fmaxf(decf(smax2[bh * 2 + 1]), sv) + dv);   // identical to part pass
        float w = __expf(lrelu(sv + dv) - m);
        size_t p0 = ((size_t)bh * 2) * NSEC + i_;
        float Z = pZS[p0] + pZS[p0 + NSEC] + w;
        wsv[h] = w; invZv[h] = 1.f / Z;
    }
    size_t xrow = ((size_t)b * NNODES + i_) * FG;

    #define FC0_LOAD_A(IT, DEST) {                                            \
        int f0 = (IT) * 16 + ak; int hh = f0 >> 5; int fh = f0 & 31;          \
        size_t p0_ = ((size_t)(b * 8 + hh * 2)) * NSEC + i_;                  \
        float4 pf0 = *(const float4*)&pfeatS[p0_ * 32 + fh];                  \
        float4 pf1 = *(const float4*)&pfeatS[(p0_ + NSEC) * 32 + fh];         \
        float4 xv = *(const float4*)&xp2[xrow + hh * 32 + fh];                \
        float4 gb = *(const float4*)&gatB[hh * 32 + fh];                      \
        float w_ = wsv[hh], z_ = invZv[hh];                                   \
        DEST.x = fmaxf((pf0.x + pf1.x + w_ * xv.x) * z_ + gb.x, 0.f);         \
        DEST.y = fmaxf((pf0.y + pf1.y + w_ * xv.y) * z_ + gb.y, 0.f);         \
        DEST.z = fmaxf((pf0.z + pf1.z + w_ * xv.z) * z_ + gb.z, 0.f);         \
        DEST.w = fmaxf((pf0.w + pf1.w + w_ * xv.w) * z_ + gb.w, 0.f);         \
    }

    {
        float4 a; FC0_LOAD_A(0, a)
        float4 bb = *(const float4*)(Bbase);
        As[0][ak + 0][am] = a.x; As[0][ak + 1][am] = a.y;
        As[0][ak + 2][am] = a.z; As[0][ak + 3][am] = a.w;
        *(float4*)&Bs[0][bk][bn] = bb;
    }
    __syncthreads();
    int nT = K >> 4;   // 8
    #pragma unroll 2
    for (int it = 1; it < nT; it++) {
        float4 a2; FC0_LOAD_A(it, a2)
        float4 b2 = *(const float4*)(Bbase + (size_t)it * 16 * N);
        int pb = (it - 1) & 1;
        #pragma unroll
        for (int k = 0; k < 16; k++) {
            float4 a4 = *(const float4*)&As[pb][k][ty << 2];
            float4 b4 = *(const float4*)&Bs[pb][k][tx << 2];
            float av[4] = {a4.x, a4.y, a4.z, a4.w};
            float bv[4] = {b4.x, b4.y, b4.z, b4.w};
            #pragma unroll
            for (int i = 0; i < 4; i++)
                #pragma unroll
                for (int j = 0; j < 4; j++)
                    acc[i][j] = fmaf(av[i], bv[j], acc[i][j]);
        }
        int cb = it & 1;
        As[cb][ak + 0][am] = a2.x; As[cb][ak + 1][am] = a2.y;
        As[cb][ak + 2][am] = a2.z; As[cb][ak + 3][am] = a2.w;
        *(float4*)&Bs[cb][bk][bn] = b2;
        __syncthreads();
    }
    {
        int pb = (nT - 1) & 1;
        #pragma unroll
        for (int k = 0; k < 16; k++) {
            float4 a4 = *(const float4*)&As[pb][k][ty << 2];
            float4 b4 = *(const float4*)&Bs[pb][k][tx << 2];
            float av[4] = {a4.x, a4.y, a4.z, a4.w};
            float bv[4] = {b4.x, b4.y, b4.z, b4.w};
            #pragma unroll
            for (int i = 0; i < 4; i++)
                #pragma unroll
                for (int j = 0; j < 4; j++)
                    acc[i][j] = fmaf(av[i], bv[j], acc[i][j]);
        }
    }
    #pragma unroll
    for (int i = 0; i < 4; i++) {
        int row = m0 + (ty << 2) + i;
        #pragma unroll
        for (int j = 0; j < 4; j++) {
            int col = n0 + (tx << 2) + j;
            float v = acc[i][j] + bias[col];
            C[(size_t)row * N + col] = fmaxf(v, 0.f);
        }
    }
}

// ---------------- fused ratio + scale/threshold + smax reset ---------------
__global__ void scale_ratio_kernel(float4* __restrict__ C, const float* __restrict__ pP,
                                   const float* __restrict__ pT, const float* __restrict__ part,
                                   unsigned* __restrict__ smaxu)
{
    __shared__ float shPs, shPps;
    int tid = threadIdx.x;
    int idx = blockIdx.x * 256 + tid;        // 262144 float4s
    int b = idx >> 16;
    int warp = tid >> 5, lane = tid & 31;
    if (blockIdx.x == 0 && tid >= 128 && tid < 192)
        smaxu[tid - 128] = 0u;               // reset for next replay
    if (warp == 0) {
        float ps = part[b * 64 + lane] + part[b * 64 + 32 + lane];
        ps = warpSum(ps);
        if (lane == 0) shPs = ps;
    } else if (warp == 1) {
        float pps = 0.f;
        #pragma unroll
        for (int k = 0; k < 8; k++) pps += pP[b * 256 + lane + 32 * k];
        pps = warpSum(pps);
        if (lane == 0) shPps = pps;
    }
    __syncthreads();
    float rr = fminf(fmaxf(pT[0] - shPps, 0.f) / (shPs + 1e-5f), 1.f);
    float4 v = C[idx];
    v.x *= rr; v.y *= rr; v.z *= rr; v.w *= rr;
    v.x = (v.x > 0.001f) ? v.x : 0.f;
    v.y = (v.y > 0.001f) ? v.y : 0.f;
    v.z = (v.z > 0.001f) ? v.z : 0.f;
    v.w = (v.w > 0.001f) ? v.w : 0.f;
    C[idx] = v;
}

// ---------------- launch ----------------------------------------------------
extern "C" void kernel_launch(void* const* d_in, const int* in_sizes, int n_in,
                              void* d_out, int out_size)
{
    const float* h   = (const float*)d_in[0];
    const float* pP  = (const float*)d_in[1];
    const float* pT  = (const float*)d_in[2];
    const float* W0  = (const float*)d_in[3];
    const float* b0  = (const float*)d_in[4];
    const float* as0 = (const float*)d_in[5];
    const float* ad0 = (const float*)d_in[6];
    const float* W1  = (const float*)d_in[7];
    const float* b1  = (const float*)d_in[8];
    const float* as1 = (const float*)d_in[9];
    const float* ad1 = (const float*)d_in[10];
    const float* Wf0 = (const float*)d_in[11];
    const float* bf0 = (const float*)d_in[12];
    const float* Wf1 = (const float*)d_in[13];
    const float* bf1 = (const float*)d_in[14];
    float* out = (float*)d_out;

    float* base = nullptr;
    cudaGetSymbolAddress((void**)&base, g_scratch);
    float* xp1    = base;                   // 786432
    float* x1     = xp1 + 786432;           // 786432
    float* xp2    = x1 + 786432;            // 786432
    float* z      = xp2 + 786432;           // 1048576
    float* s1     = z + 1048576;            // 24576
    float* d1     = s1 + 24576;
    float* s2     = d1 + 24576;
    float* d2     = s2 + 24576;
    unsigned* smaxu = (unsigned*)(d2 + 24576);  // 64
    float* pfeat  = d2 + 24576 + 64;        // beam partials: 16*8*256*32 = 1048576
    float* pZ     = pfeat + 1048576;        // 32768
    float* pfeatS = pZ + 32768;             // sec partials: 16*2*1024*32 = 1048576
    float* pZS    = pfeatS + 1048576;       // 32768
    float* part   = pZS + 32768;            // 256
    unsigned* smax1u = smaxu;
    unsigned* smax2u = smaxu + 32;

    cudaStream_t sA;
    cudaStreamCreateWithFlags(&sA, cudaStreamNonBlocking);
    cudaEvent_t evFork, evJoin;
    cudaEventCreateWithFlags(&evFork, cudaEventDisableTiming);
    cudaEventCreateWithFlags(&evJoin, cudaEventDisableTiming);

    // Layer 1 GEMM (fused sd + segment-max; smaxu reset by prior replay's
    // scale_ratio; zero-initialized device memory on the first call).
    gemm_kernel<<<dim3(2, 96), 256>>>(h, W0, nullptr, xp1, FG, FG, 24, 24, 0, 0,
                                      nullptr, as0, ad0, s1, d1, smax1u);
    // Fork: beam path + gemm2 beam tiles on sA; sec path + gemm2 sec tiles on 0.
    cudaEventRecord(evFork, 0);
    cudaStreamWaitEvent(sA, evFork, 0);
    beam_agg_part_kernel<<<dim3(4, 8, 16), 256, 0, sA>>>(xp1, s1, d1, smax1u, pfeat, pZ);
    beam_combine_kernel<<<dim3(32, 16), 256, 0, sA>>>(xp1, s1, d1, smax1u, pfeat, pZ, b0, x1);
    gemm_kernel<<<dim3(2, 16), 256, 0, sA>>>(x1, W1, nullptr, xp2, FG, FG, 4, 24, 16, 0,
                                             nullptr, as1, ad1, s2, d2, smax2u);
    sec_agg_part_kernel<<<dim3(16, 2, 16), 256>>>(xp1, s1, d1, smax1u, pfeatS, pZS);
    sec_combine_kernel<<<dim3(128, 16), 256>>>(xp1, s1, d1, smax1u, pfeatS, pZS, b0, x1,
                                               NNODES * FG);
    gemm_kernel<<<dim3(2, 64), 256>>>(x1, W1, nullptr, xp2, FG, FG, 16, 24, 0, 0,
                                      nullptr, as1, ad1, s2, d2, smax2u);
    cudaEventRecord(evJoin, sA);
    cudaStreamWaitEvent(0, evJoin, 0);

    // Layer-2 sec aggregation partials (needs beam rows of xp2/s2 + smax2)
    sec_agg_part_kernel<<<dim3(16, 2, 16), 256>>>(xp2, s2, d2, smax2u, pfeatS, pZS);

    // FC stack (sec combine fused into FC0's A-loader)
    fc0_fused_kernel<<<dim3(4, 64), 256>>>(pfeatS, pZS, xp2, s2, d2, smax2u, b1,
                                           Wf0, bf0, z);
    gemm_kernel<<<dim3(4, 64), 256>>>(z, Wf1, bf1, out, 256, 256, 64, 64, 0, 1,
                                      part, nullptr, nullptr, nullptr, nullptr, nullptr);

    // Fused ratio + threshold (+ smax reset for next replay)
    scale_ratio_kernel<<<1024, 256>>>((float4*)out, pP, pT, part, smaxu);
}